// round 15
// baseline (speedup 1.0000x reference)
#include <cuda_runtime.h>
#include <math.h>
#include <stddef.h>
#include <stdint.h>

// ---------------- problem constants (fixed shapes) ----------------
constexpr int Bn   = 4;
constexpr int Cc   = 512;
constexpr int Dd   = 512;
constexpr int Tt   = 16;
constexpr int Nn   = Bn * Tt;      // 64 sequences
constexpr int Tk   = Cc;           // 512 tokens
constexpr int Hh   = 8;
constexpr int HD   = 64;
constexpr int DQKV = 3 * Dd;       // 1536
constexpr int DFF  = 2048;
constexpr int Rr   = 128;
constexpr int T2   = Tk / 2;       // 256
constexpr int TNEW = Tk - Rr;      // 384
constexpr int M1   = Nn * Tk;      // 32768
constexpr int M2   = Nn * TNEW;    // 24576
constexpr int NROW = Nn * Hh * Tk; // 262144 attention rows

// ---------------- scratch (__device__ globals; no allocation) ----------------
__device__ float  g_h   [(size_t)M1 * Dd];
__device__ float  g_y   [(size_t)M1 * Dd];
__device__ float  g_qkv [(size_t)M1 * DQKV];
__device__ float  g_kf  [(size_t)M1 * Dd];          // fp32-exact k block (routing + attention K)
__device__ float  g_S   [(size_t)Nn * Hh * Tk * Tk];
__device__ float2 g_stats[NROW];                     // per-row {max, 1/sum}
__device__ float  g_m   [(size_t)M1 * HD];
__device__ float  g_hm  [(size_t)M2 * Dd];
__device__ float  g_nmax[Nn * T2];
__device__ int    g_nidx[Nn * T2];
__device__ int    g_srcI[Nn * Rr];
__device__ int    g_dstI[Nn * Rr];
__device__ int    g_unmI[Nn * Rr];

// ---------------- tf32 / async helpers ----------------
__device__ __forceinline__ float to_tf32(float x) {
    uint32_t u;
    asm("cvt.rna.tf32.f32 %0, %1;" : "=r"(u) : "f"(x));
    return __uint_as_float(u);
}
__device__ __forceinline__ float4 to_tf32_4(float4 v) {
    v.x = to_tf32(v.x); v.y = to_tf32(v.y); v.z = to_tf32(v.z); v.w = to_tf32(v.w);
    return v;
}
__device__ __forceinline__ float4 exp_stats_4(float4 v, float2 st) {
    v.x = __expf(v.x - st.x) * st.y;
    v.y = __expf(v.y - st.x) * st.y;
    v.z = __expf(v.z - st.x) * st.y;
    v.w = __expf(v.w - st.x) * st.y;
    return v;
}
__device__ __forceinline__ void mma_tf32(float* c, const uint32_t* a, const uint32_t* b) {
    asm volatile(
        "mma.sync.aligned.m16n8k8.row.col.f32.tf32.tf32.f32 "
        "{%0,%1,%2,%3}, {%4,%5,%6,%7}, {%8,%9}, {%0,%1,%2,%3};"
        : "+f"(c[0]), "+f"(c[1]), "+f"(c[2]), "+f"(c[3])
        : "r"(a[0]), "r"(a[1]), "r"(a[2]), "r"(a[3]), "r"(b[0]), "r"(b[1]));
}
__device__ __forceinline__ uint32_t fbits(float x) { return __float_as_uint(x); }
__device__ __forceinline__ void cp_async16(void* s, const void* g) {
    uint32_t sa = (uint32_t)__cvta_generic_to_shared(s);
    asm volatile("cp.async.ca.shared.global [%0], [%1], 16;\n" :: "r"(sa), "l"(g));
}
__device__ __forceinline__ void cp_commit() {
    asm volatile("cp.async.commit_group;\n");
}
template<int N>
__device__ __forceinline__ void cp_wait() {
    asm volatile("cp.async.wait_group %0;\n" :: "n"(N));
}

// ---------------- permutes ----------------
__global__ void permute_in_kernel(const float* __restrict__ x) {
    __shared__ float tile[256 * 17];
    int b = blockIdx.z, c = blockIdx.y, d0 = blockIdx.x * 256;
    int tid = threadIdx.x;
    const float* src = x + ((size_t)(b * Cc + c) * Dd + d0) * Tt;
    #pragma unroll
    for (int it = 0; it < 16; it++) {
        int l = tid + it * 256;
        tile[(l >> 4) * 17 + (l & 15)] = src[l];
    }
    __syncthreads();
    #pragma unroll
    for (int tt = 0; tt < 16; tt++) {
        g_h[((size_t)(b * Tt + tt) * Tk + c) * Dd + d0 + tid] = tile[tid * 17 + tt];
    }
}

__global__ void permute_out_kernel(float* __restrict__ out) {
    __shared__ float tile[256 * 17];
    int b = blockIdx.z, tn = blockIdx.y, d0 = blockIdx.x * 256;
    int tid = threadIdx.x;
    #pragma unroll
    for (int tt = 0; tt < 16; tt++) {
        tile[tid * 17 + tt] = g_h[((size_t)(b * Tt + tt) * TNEW + tn) * Dd + d0 + tid];
    }
    __syncthreads();
    float* dst = out + ((size_t)(b * TNEW + tn) * Dd + d0) * Tt;
    #pragma unroll
    for (int it = 0; it < 16; it++) {
        int l = tid + it * 256;
        dst[l] = tile[(l >> 4) * 17 + (l & 15)];
    }
}

// ---------------- layernorm ----------------
__global__ void ln_kernel(const float* __restrict__ in, float* __restrict__ out,
                          const float* __restrict__ w, const float* __restrict__ bb) {
    int row = blockIdx.x;
    int tid = threadIdx.x;
    const float* x = in + (size_t)row * Dd;
    float v[4];
    float s = 0.f;
    #pragma unroll
    for (int i = 0; i < 4; i++) { v[i] = x[tid + i * 128]; s += v[i]; }
    __shared__ float red[4];
    #pragma unroll
    for (int o = 16; o; o >>= 1) s += __shfl_xor_sync(0xffffffffu, s, o);
    if ((tid & 31) == 0) red[tid >> 5] = s;
    __syncthreads();
    s = red[0] + red[1] + red[2] + red[3];
    float mean = s * (1.f / 512.f);
    float s2 = 0.f;
    #pragma unroll
    for (int i = 0; i < 4; i++) { float t = v[i] - mean; s2 += t * t; }
    #pragma unroll
    for (int o = 16; o; o >>= 1) s2 += __shfl_xor_sync(0xffffffffu, s2, o);
    __syncthreads();
    if ((tid & 31) == 0) red[tid >> 5] = s2;
    __syncthreads();
    s2 = red[0] + red[1] + red[2] + red[3];
    float inv = rsqrtf(s2 * (1.f / 512.f) + 1e-6f);
    float* o = out + (size_t)row * Dd;
    #pragma unroll
    for (int i = 0; i < 4; i++) {
        int c = tid + i * 128;
        o[c] = (v[i] - mean) * inv * w[c] + bb[c];
    }
}

// ---------------- fp32 GEMM (routing path; bit-stable serial-k accumulation) ---
template<int BM, int BN, int BK, int TM, int TN, bool TRANSB, bool GELU, bool RESID>
__global__ __launch_bounds__(256, 2) void gemm_kernel(
    int K,
    const float* __restrict__ A, int lda, long long aSN, long long aSH,
    const float* __restrict__ B, int ldb, long long bSN, long long bSH,
    float*       __restrict__ C, int ldc, long long cSN, long long cSH,
    int Hdiv, const float* __restrict__ bias, float alpha,
    const float* __restrict__ resid, int ldr)
{
    constexpr int SEGM = TM / 4;
    constexpr int SEGN = TN / 4;
    static_assert(BM == 64 * SEGM && BN == 64 * SEGN, "layout requires 16x16 threads");
    __shared__ __align__(16) float As[2][BK][BM + 4];
    __shared__ __align__(16) float Bs[2][BK][BN + 4];
    int z = blockIdx.z;
    int zn = z / Hdiv, zh = z - zn * Hdiv;
    A += zn * aSN + zh * aSH;
    B += zn * bSN + zh * bSH;
    C += zn * cSN + zh * cSH;
    int row0 = blockIdx.y * BM, col0 = blockIdx.x * BN;
    int tid = threadIdx.x;
    int tx = tid % 16, ty = tid / 16;

    constexpr int KV = BK / 4;
    constexpr int AV = BM * BK / 1024;
    constexpr int BV = BN * BK / 1024;

    int am = tid / KV,  ak = (tid % KV) * 4;
    int am2 = (tid + 256) / KV, ak2 = ((tid + 256) % KV) * 4;
    int bn_t = tid / KV,            bk_t = (tid % KV) * 4;
    int bn_t2 = (tid + 256) / KV,   bk_t2 = ((tid + 256) % KV) * 4;
    int bk_n = tid / (BN / 4),      bn_n = (tid % (BN / 4)) * 4;
    int bk_n2 = (tid + 256) / (BN / 4), bn_n2 = ((tid + 256) % (BN / 4)) * 4;

    float4 ra[AV], rb[BV];
    float acc[TM][TN];
    #pragma unroll
    for (int i = 0; i < TM; i++)
        #pragma unroll
        for (int j = 0; j < TN; j++) acc[i][j] = 0.f;

    float (*Asc)[BM + 4] = As[0];
    float (*Asn)[BM + 4] = As[1];
    float (*Bsc)[BN + 4] = Bs[0];
    float (*Bsn)[BN + 4] = Bs[1];

    {
        ra[0] = *(const float4*)(A + (size_t)(row0 + am) * lda + ak);
        if (AV > 1) ra[1] = *(const float4*)(A + (size_t)(row0 + am2) * lda + ak2);
        if (TRANSB) {
            rb[0] = *(const float4*)(B + (size_t)(col0 + bn_t) * ldb + bk_t);
            if (BV > 1) rb[1] = *(const float4*)(B + (size_t)(col0 + bn_t2) * ldb + bk_t2);
        } else {
            rb[0] = *(const float4*)(B + (size_t)bk_n * ldb + col0 + bn_n);
            if (BV > 1) rb[1] = *(const float4*)(B + (size_t)bk_n2 * ldb + col0 + bn_n2);
        }
        Asc[ak + 0][am] = ra[0].x; Asc[ak + 1][am] = ra[0].y;
        Asc[ak + 2][am] = ra[0].z; Asc[ak + 3][am] = ra[0].w;
        if (AV > 1) {
            Asc[ak2 + 0][am2] = ra[1].x; Asc[ak2 + 1][am2] = ra[1].y;
            Asc[ak2 + 2][am2] = ra[1].z; Asc[ak2 + 3][am2] = ra[1].w;
        }
        if (TRANSB) {
            Bsc[bk_t + 0][bn_t] = rb[0].x; Bsc[bk_t + 1][bn_t] = rb[0].y;
            Bsc[bk_t + 2][bn_t] = rb[0].z; Bsc[bk_t + 3][bn_t] = rb[0].w;
            if (BV > 1) {
                Bsc[bk_t2 + 0][bn_t2] = rb[1].x; Bsc[bk_t2 + 1][bn_t2] = rb[1].y;
                Bsc[bk_t2 + 2][bn_t2] = rb[1].z; Bsc[bk_t2 + 3][bn_t2] = rb[1].w;
            }
        } else {
            *(float4*)&Bsc[bk_n][bn_n] = rb[0];
            if (BV > 1) *(float4*)&Bsc[bk_n2][bn_n2] = rb[1];
        }
    }
    __syncthreads();

    for (int k0 = BK; k0 < K; k0 += BK) {
        ra[0] = *(const float4*)(A + (size_t)(row0 + am) * lda + k0 + ak);
        if (AV > 1) ra[1] = *(const float4*)(A + (size_t)(row0 + am2) * lda + k0 + ak2);
        if (TRANSB) {
            rb[0] = *(const float4*)(B + (size_t)(col0 + bn_t) * ldb + k0 + bk_t);
            if (BV > 1) rb[1] = *(const float4*)(B + (size_t)(col0 + bn_t2) * ldb + k0 + bk_t2);
        } else {
            rb[0] = *(const float4*)(B + (size_t)(k0 + bk_n) * ldb + col0 + bn_n);
            if (BV > 1) rb[1] = *(const float4*)(B + (size_t)(k0 + bk_n2) * ldb + col0 + bn_n2);
        }
        #pragma unroll
        for (int k = 0; k < BK; k++) {
            float rm[TM], rn[TN];
            #pragma unroll
            for (int s = 0; s < SEGM; s++)
                *(float4*)&rm[s * 4] = *(const float4*)&Asc[k][ty * 4 + s * 64];
            #pragma unroll
            for (int s = 0; s < SEGN; s++)
                *(float4*)&rn[s * 4] = *(const float4*)&Bsc[k][tx * 4 + s * 64];
            #pragma unroll
            for (int i = 0; i < TM; i++)
                #pragma unroll
                for (int j = 0; j < TN; j++)
                    acc[i][j] += rm[i] * rn[j];
        }
        Asn[ak + 0][am] = ra[0].x; Asn[ak + 1][am] = ra[0].y;
        Asn[ak + 2][am] = ra[0].z; Asn[ak + 3][am] = ra[0].w;
        if (AV > 1) {
            Asn[ak2 + 0][am2] = ra[1].x; Asn[ak2 + 1][am2] = ra[1].y;
            Asn[ak2 + 2][am2] = ra[1].z; Asn[ak2 + 3][am2] = ra[1].w;
        }
        if (TRANSB) {
            Bsn[bk_t + 0][bn_t] = rb[0].x; Bsn[bk_t + 1][bn_t] = rb[0].y;
            Bsn[bk_t + 2][bn_t] = rb[0].z; Bsn[bk_t + 3][bn_t] = rb[0].w;
            if (BV > 1) {
                Bsn[bk_t2 + 0][bn_t2] = rb[1].x; Bsn[bk_t2 + 1][bn_t2] = rb[1].y;
                Bsn[bk_t2 + 2][bn_t2] = rb[1].z; Bsn[bk_t2 + 3][bn_t2] = rb[1].w;
            }
        } else {
            *(float4*)&Bsn[bk_n][bn_n] = rb[0];
            if (BV > 1) *(float4*)&Bsn[bk_n2][bn_n2] = rb[1];
        }
        __syncthreads();
        float (*t1)[BM + 4] = Asc; Asc = Asn; Asn = t1;
        float (*t2)[BN + 4] = Bsc; Bsc = Bsn; Bsn = t2;
    }
    #pragma unroll
    for (int k = 0; k < BK; k++) {
        float rm[TM], rn[TN];
        #pragma unroll
        for (int s = 0; s < SEGM; s++)
            *(float4*)&rm[s * 4] = *(const float4*)&Asc[k][ty * 4 + s * 64];
        #pragma unroll
        for (int s = 0; s < SEGN; s++)
            *(float4*)&rn[s * 4] = *(const float4*)&Bsc[k][tx * 4 + s * 64];
        #pragma unroll
        for (int i = 0; i < TM; i++)
            #pragma unroll
            for (int j = 0; j < TN; j++)
                acc[i][j] += rm[i] * rn[j];
    }

    #pragma unroll
    for (int si = 0; si < SEGM; si++) {
        #pragma unroll
        for (int i2 = 0; i2 < 4; i2++) {
            int r = row0 + ty * 4 + si * 64 + i2;
            int i = si * 4 + i2;
            #pragma unroll
            for (int sj = 0; sj < SEGN; sj++) {
                int c = col0 + tx * 4 + sj * 64;
                float4 v;
                v.x = acc[i][sj * 4 + 0] * alpha;
                v.y = acc[i][sj * 4 + 1] * alpha;
                v.z = acc[i][sj * 4 + 2] * alpha;
                v.w = acc[i][sj * 4 + 3] * alpha;
                if (bias) {
                    float4 bv = *(const float4*)(bias + c);
                    v.x += bv.x; v.y += bv.y; v.z += bv.z; v.w += bv.w;
                }
                if (GELU) {
                    v.x = 0.5f * v.x * (1.f + erff(v.x * 0.70710678118654752f));
                    v.y = 0.5f * v.y * (1.f + erff(v.y * 0.70710678118654752f));
                    v.z = 0.5f * v.z * (1.f + erff(v.z * 0.70710678118654752f));
                    v.w = 0.5f * v.w * (1.f + erff(v.w * 0.70710678118654752f));
                }
                if (RESID) {
                    float4 rv = *(const float4*)(resid + (size_t)r * ldr + c);
                    v.x += rv.x; v.y += rv.y; v.z += rv.z; v.w += rv.w;
                }
                *(float4*)(C + (size_t)r * ldc + c) = v;
            }
        }
    }
}

// ---------------- tf32 async GEMM: cp.async 3-stage, generalized BM ------------
// Raw fp32 staged via LDGSTS; HMMA.TF32 truncates operands. A and B both
// K-contiguous row-major (TRANSB-style B).
template<int BM, int BN, int BK, int WM, int WN, bool GELU, bool RESID, int STAGES, int MINB>
__global__ __launch_bounds__(256, MINB) void tgemm_async_kernel(
    int K,
    const float* __restrict__ A, int lda, long long aSN, long long aSH,
    const float* __restrict__ B, int ldb, long long bSN, long long bSH,
    float*       __restrict__ C, int ldc, long long cSN, long long cSH,
    int Hdiv, const float* __restrict__ bias, float alpha,
    const float* __restrict__ resid, int ldr)
{
    constexpr int KP  = BK + 4;
    constexpr int WTM = BM / WM;
    constexpr int WTN = BN / WN;
    constexpr int MF  = WTM / 16;
    constexpr int NF  = WTN / 8;
    constexpr int KV  = BK / 4;
    constexpr int AV  = BM / 64;
    constexpr int BV  = BN / 64;
    static_assert(WM * WN == 8, "8 warps");
    static_assert(BK == 16, "fixed BK");

    extern __shared__ float smem[];
    float* As = smem;                          // STAGES * BM * KP
    float* Bs = smem + STAGES * BM * KP;       // STAGES * BN * KP

    int z = blockIdx.z;
    int zn = z / Hdiv, zh = z - zn * Hdiv;
    A += zn * aSN + zh * aSH;
    B += zn * bSN + zh * bSH;
    C += zn * cSN + zh * cSH;
    int row0 = blockIdx.y * BM, col0 = blockIdx.x * BN;
    int tid = threadIdx.x;
    int wid = tid >> 5, lane = tid & 31;
    int wm = (wid / WN) * WTM, wn = (wid % WN) * WTN;
    int gid = lane >> 2, tig = lane & 3;

    int am = tid / KV, ak = (tid % KV) * 4;

    const float* Ap[AV];
    const float* Bp[BV];
    float* Asd[AV];
    float* Bsd[BV];
    #pragma unroll
    for (int v = 0; v < AV; v++) {
        Ap[v]  = A + (size_t)(row0 + am + v * 64) * lda + ak;
        Asd[v] = As + (size_t)(am + v * 64) * KP + ak;
    }
    #pragma unroll
    for (int v = 0; v < BV; v++) {
        Bp[v]  = B + (size_t)(col0 + am + v * 64) * ldb + ak;
        Bsd[v] = Bs + (size_t)(am + v * 64) * KP + ak;
    }

    float acc[MF][NF][4];
    #pragma unroll
    for (int f = 0; f < MF; f++)
        #pragma unroll
        for (int j = 0; j < NF; j++)
            #pragma unroll
            for (int q = 0; q < 4; q++) acc[f][j][q] = 0.f;

    const int NC = K / BK;

    // prologue: issue first STAGES-1 chunks
    #pragma unroll
    for (int s = 0; s < STAGES - 1; s++) {
        int k0 = s * BK;
        #pragma unroll
        for (int v = 0; v < AV; v++) cp_async16(Asd[v] + s * BM * KP, Ap[v] + k0);
        #pragma unroll
        for (int v = 0; v < BV; v++) cp_async16(Bsd[v] + s * BN * KP, Bp[v] + k0);
        cp_commit();
    }

    for (int c = 0; c < NC; c++) {
        cp_wait<STAGES - 2>();
        __syncthreads();
        int cn = c + STAGES - 1;
        if (cn < NC) {
            int s = cn % STAGES;
            int k0 = cn * BK;
            #pragma unroll
            for (int v = 0; v < AV; v++) cp_async16(Asd[v] + s * BM * KP, Ap[v] + k0);
            #pragma unroll
            for (int v = 0; v < BV; v++) cp_async16(Bsd[v] + s * BN * KP, Bp[v] + k0);
        }
        cp_commit();
        int cs = c % STAGES;
        const uint32_t* Ast = (const uint32_t*)(As + (size_t)cs * BM * KP);
        const uint32_t* Bst = (const uint32_t*)(Bs + (size_t)cs * BN * KP);
        #pragma unroll
        for (int kk = 0; kk < BK; kk += 8) {
            uint32_t af[MF][4], bf[NF][2];
            #pragma unroll
            for (int f = 0; f < MF; f++) {
                const uint32_t* ap = Ast + (size_t)(wm + f * 16 + gid) * KP + kk + tig;
                af[f][0] = ap[0];
                af[f][1] = ap[8 * KP];
                af[f][2] = ap[4];
                af[f][3] = ap[8 * KP + 4];
            }
            #pragma unroll
            for (int j = 0; j < NF; j++) {
                const uint32_t* bp = Bst + (size_t)(wn + j * 8 + gid) * KP + kk + tig;
                bf[j][0] = bp[0];
                bf[j][1] = bp[4];
            }
            #pragma unroll
            for (int f = 0; f < MF; f++)
                #pragma unroll
                for (int j = 0; j < NF; j++)
                    mma_tf32(acc[f][j], af[f], bf[j]);
        }
    }

    // ---- epilogue ----
    #pragma unroll
    for (int f = 0; f < MF; f++) {
        #pragma unroll
        for (int half = 0; half < 2; half++) {
            int r = row0 + wm + f * 16 + gid + half * 8;
            #pragma unroll
            for (int j = 0; j < NF; j++) {
                int c = col0 + wn + j * 8 + tig * 2;
                float vx = acc[f][j][half * 2 + 0] * alpha;
                float vy = acc[f][j][half * 2 + 1] * alpha;
                if (bias) { vx += bias[c]; vy += bias[c + 1]; }
                if (GELU) {
                    vx = 0.5f * vx * (1.f + erff(vx * 0.70710678118654752f));
                    vy = 0.5f * vy * (1.f + erff(vy * 0.70710678118654752f));
                }
                if (RESID) {
                    float2 rv = *(const float2*)(resid + (size_t)r * ldr + c);
                    vx += rv.x; vy += rv.y;
                }
                float2 v; v.x = vx; v.y = vy;
                *(float2*)(C + (size_t)r * ldc + c) = v;
            }
        }
    }
}

// ---------------- tf32 tensor-core GEMM (PV / EXPA path) ----------------------
template<int BM, int BN, int BK, int WM, int WN, bool TRANSB, bool GELU, bool RESID, bool EXPA, int MINB>
__global__ __launch_bounds__(256, MINB) void tgemm_kernel(
    int K,
    const float* __restrict__ A, int lda, long long aSN, long long aSH,
    const float* __restrict__ B, int ldb, long long bSN, long long bSH,
    float*       __restrict__ C, int ldc, long long cSN, long long cSH,
    int Hdiv, const float* __restrict__ bias, float alpha,
    const float* __restrict__ resid, int ldr,
    const float2* __restrict__ stats)
{
    constexpr int KP  = BK + 4;
    constexpr int WTM = BM / WM;
    constexpr int WTN = BN / WN;
    constexpr int MF  = WTM / 16;
    constexpr int NF  = WTN / 8;
    constexpr int KV  = BK / 4;
    constexpr int AV  = BM * BK / 1024;
    constexpr int BV  = BN * BK / 1024;
    constexpr int BROWS = 1024 / BN;
    static_assert(WM * WN == 8, "8 warps");

    __shared__ __align__(16) float As[2][BM][KP];
    __shared__ __align__(16) float Bs[2][BN][KP];

    int z = blockIdx.z;
    int zn = z / Hdiv, zh = z - zn * Hdiv;
    A += zn * aSN + zh * aSH;
    B += zn * bSN + zh * bSH;
    C += zn * cSN + zh * cSH;
    int row0 = blockIdx.y * BM, col0 = blockIdx.x * BN;
    int tid = threadIdx.x;
    int wid = tid >> 5, lane = tid & 31;
    int wm = (wid / WN) * WTM, wn = (wid % WN) * WTN;
    int gid = lane >> 2, tig = lane & 3;

    int am = tid / KV,  ak = (tid % KV) * 4;
    int bn_t = tid / KV, bk_t = (tid % KV) * 4;
    int bk_n = tid / (BN / 4), bn_n = (tid % (BN / 4)) * 4;

    float2 st[AV];
    #pragma unroll
    for (int v = 0; v < AV; v++) st[v] = make_float2(0.f, 1.f);
    if (EXPA) {
        #pragma unroll
        for (int v = 0; v < AV; v++)
            st[v] = stats[(size_t)z * Tk + row0 + am + v * 64];
    }

    float4 ra[AV], rb[BV];
    float acc[MF][NF][4];
    #pragma unroll
    for (int f = 0; f < MF; f++)
        #pragma unroll
        for (int j = 0; j < NF; j++)
            #pragma unroll
            for (int q = 0; q < 4; q++) acc[f][j][q] = 0.f;

    float (*Asc)[KP] = As[0];
    float (*Asn)[KP] = As[1];
    float (*Bsc)[KP] = Bs[0];
    float (*Bsn)[KP] = Bs[1];

    {
        #pragma unroll
        for (int v = 0; v < AV; v++)
            ra[v] = *(const float4*)(A + (size_t)(row0 + am + v * 64) * lda + ak);
        if (TRANSB) {
            #pragma unroll
            for (int v = 0; v < BV; v++)
                rb[v] = *(const float4*)(B + (size_t)(col0 + bn_t + v * 64) * ldb + bk_t);
        } else {
            #pragma unroll
            for (int v = 0; v < BV; v++)
                rb[v] = *(const float4*)(B + (size_t)(bk_n + v * BROWS) * ldb + col0 + bn_n);
        }
        #pragma unroll
        for (int v = 0; v < AV; v++) {
            float4 t = ra[v];
            if (EXPA) t = exp_stats_4(t, st[v]);
            *(float4*)&Asc[am + v * 64][ak] = to_tf32_4(t);
        }
        if (TRANSB) {
            #pragma unroll
            for (int v = 0; v < BV; v++)
                *(float4*)&Bsc[bn_t + v * 64][bk_t] = to_tf32_4(rb[v]);
        } else {
            #pragma unroll
            for (int v = 0; v < BV; v++) {
                float4 t = to_tf32_4(rb[v]);
                int bk2 = bk_n + v * BROWS;
                Bsc[bn_n + 0][bk2] = t.x; Bsc[bn_n + 1][bk2] = t.y;
                Bsc[bn_n + 2][bk2] = t.z; Bsc[bn_n + 3][bk2] = t.w;
            }
        }
    }
    __syncthreads();

    for (int k0 = BK; k0 < K; k0 += BK) {
        #pragma unroll
        for (int v = 0; v < AV; v++)
            ra[v] = *(const float4*)(A + (size_t)(row0 + am + v * 64) * lda + k0 + ak);
        if (TRANSB) {
            #pragma unroll
            for (int v = 0; v < BV; v++)
                rb[v] = *(const float4*)(B + (size_t)(col0 + bn_t + v * 64) * ldb + k0 + bk_t);
        } else {
            #pragma unroll
            for (int v = 0; v < BV; v++)
                rb[v] = *(const float4*)(B + (size_t)(k0 + bk_n + v * BROWS) * ldb + col0 + bn_n);
        }
        #pragma unroll
        for (int kk = 0; kk < BK; kk += 8) {
            uint32_t af[MF][4], bf[NF][2];
            #pragma unroll
            for (int f = 0; f < MF; f++) {
                const float* ap = &Asc[wm + f * 16 + gid][kk + tig];
                af[f][0] = fbits(ap[0]);
                af[f][1] = fbits(ap[8 * KP]);
                af[f][2] = fbits(ap[4]);
                af[f][3] = fbits(ap[8 * KP + 4]);
            }
            #pragma unroll
            for (int j = 0; j < NF; j++) {
                const float* bp = &Bsc[wn + j * 8 + gid][kk + tig];
                bf[j][0] = fbits(bp[0]);
                bf[j][1] = fbits(bp[4]);
            }
            #pragma unroll
            for (int f = 0; f < MF; f++)
                #pragma unroll
                for (int j = 0; j < NF; j++)
                    mma_tf32(acc[f][j], af[f], bf[j]);
        }
        #pragma unroll
        for (int v = 0; v < AV; v++) {
            float4 t = ra[v];
            if (EXPA) t = exp_stats_4(t, st[v]);
            *(float4*)&Asn[am + v * 64][ak] = to_tf32_4(t);
        }
        if (TRANSB) {
            #pragma unroll
            for (int v = 0; v < BV; v++)
                *(float4*)&Bsn[bn_t + v * 64][bk_t] = to_tf32_4(rb[v]);
        } else {
            #pragma unroll
            for (int v = 0; v < BV; v++) {
                float4 t = to_tf32_4(rb[v]);
                int bk2 = bk_n + v * BROWS;
                Bsn[bn_n + 0][bk2] = t.x; Bsn[bn_n + 1][bk2] = t.y;
                Bsn[bn_n + 2][bk2] = t.z; Bsn[bn_n + 3][bk2] = t.w;
            }
        }
        __syncthreads();
        float (*t1)[KP] = Asc; Asc = Asn; Asn = t1;
        float (*t2)[KP] = Bsc; Bsc = Bsn; Bsn = t2;
    }
    #pragma unroll
    for (int kk = 0; kk < BK; kk += 8) {
        uint32_t af[MF][4], bf[NF][2];
        #pragma unroll
        for (int f = 0; f < MF; f++) {
            const float* ap = &Asc[wm + f * 16 + gid][kk + tig];
            af[f][0] = fbits(ap[0]);
            af[f][1] = fbits(ap[8 * KP]);
            af[f][2] = fbits(ap[4]);
            af[f][3] = fbits(ap[8 * KP + 4]);
        }
        #pragma unroll
        for (int j = 0; j < NF; j++) {
            const float* bp = &Bsc[wn + j * 8 + gid][kk + tig];
            bf[j][0] = fbits(bp[0]);
            bf[j][1] = fbits(bp[4]);
        }
        #pragma unroll
        for (int f = 0; f < MF; f++)
            #pragma unroll
            for (int j = 0; j < NF; j++)
                mma_tf32(acc[f][j], af[f], bf[j]);
    }

    #pragma unroll
    for (int f = 0; f < MF; f++) {
        #pragma unroll
        for (int half = 0; half < 2; half++) {
            int r = row0 + wm + f * 16 + gid + half * 8;
            #pragma unroll
            for (int j = 0; j < NF; j++) {
                int c = col0 + wn + j * 8 + tig * 2;
                float vx = acc[f][j][half * 2 + 0] * alpha;
                float vy = acc[f][j][half * 2 + 1] * alpha;
                if (bias) { vx += bias[c]; vy += bias[c + 1]; }
                if (GELU) {
                    vx = 0.5f * vx * (1.f + erff(vx * 0.70710678118654752f));
                    vy = 0.5f * vy * (1.f + erff(vy * 0.70710678118654752f));
                }
                if (RESID) {
                    float2 rv = *(const float2*)(resid + (size_t)r * ldr + c);
                    vx += rv.x; vy += rv.y;
                }
                float2 v; v.x = vx; v.y = vy;
                *(float2*)(C + (size_t)r * ldc + c) = v;
            }
        }
    }
}

// ---------------- metric = mean_h(k), L2-normalized (bit-stable order) ---------
__global__ void metric_kernel() {
    int token = blockIdx.x;
    int d = threadIdx.x;        // 64
    const float* base = g_kf + (size_t)token * Dd + d;
    float v = 0.f;
    #pragma unroll
    for (int h = 0; h < Hh; h++) v += base[h * HD];
    v *= 0.125f;
    float sq = v * v;
    #pragma unroll
    for (int o = 16; o; o >>= 1) sq += __shfl_xor_sync(0xffffffffu, sq, o);
    __shared__ float ws[2];
    if ((d & 31) == 0) ws[d >> 5] = sq;
    __syncthreads();
    float tot = ws[0] + ws[1];
    g_m[(size_t)token * HD + d] = v / sqrtf(tot);
}

// ---------------- softmax stats: per-row {max, 1/sum(exp)} --------------------
__global__ void softmax_stats_kernel() {
    int gw   = (blockIdx.x * blockDim.x + threadIdx.x) >> 5;
    int lane = threadIdx.x & 31;
    const float* row = g_S + (size_t)gw * Tk;
    float v[16];
    float mx = -1e30f;
    #pragma unroll
    for (int i = 0; i < 16; i++) { v[i] = row[lane + i * 32]; mx = fmaxf(mx, v[i]); }
    #pragma unroll
    for (int o = 16; o; o >>= 1) mx = fmaxf(mx, __shfl_xor_sync(0xffffffffu, mx, o));
    float s = 0.f;
    #pragma unroll
    for (int i = 0; i < 16; i++) s += __expf(v[i] - mx);
    #pragma unroll
    for (int o = 16; o; o >>= 1) s += __shfl_xor_sync(0xffffffffu, s, o);
    if (lane == 0) g_stats[gw] = make_float2(mx, 1.f / s);
}

// ---------------- node_max / node_idx ----------------
__global__ void node_kernel() {
    int n = blockIdx.y, i = blockIdx.x;
    __shared__ float a[64];
    __shared__ float sv[256];
    __shared__ int   si[256];
    int tid = threadIdx.x;
    if (tid < 64) a[tid] = g_m[((size_t)n * Tk + 2 * i) * HD + tid];
    __syncthreads();
    const float* bj = g_m + ((size_t)n * Tk + 2 * tid + 1) * HD;
    float s = 0.f;
    #pragma unroll
    for (int d = 0; d < 64; d++) s += a[d] * bj[d];
    sv[tid] = s; si[tid] = tid;
    __syncthreads();
    for (int st = 128; st; st >>= 1) {
        if (tid < st) {
            float v2 = sv[tid + st]; int i2 = si[tid + st];
            if (v2 > sv[tid] || (v2 == sv[tid] && i2 < si[tid])) { sv[tid] = v2; si[tid] = i2; }
        }
        __syncthreads();
    }
    if (tid == 0) { g_nmax[n * T2 + i] = sv[0]; g_nidx[n * T2 + i] = si[0]; }
}

// ---------------- stable descending rank sort ----------------
__global__ void sort_kernel() {
    int n = blockIdx.x, i = threadIdx.x;
    __shared__ float k[256];
    __shared__ int   se[256];
    k[i] = g_nmax[n * T2 + i];
    __syncthreads();
    float ki = k[i];
    int r = 0;
    #pragma unroll 8
    for (int j = 0; j < 256; j++) {
        float kj = k[j];
        r += (kj > ki) || (kj == ki && j < i);
    }
    se[r] = i;
    __syncthreads();
    if (i < Rr) {
        int s = se[i];
        g_srcI[n * Rr + i] = s;
        g_dstI[n * Rr + i] = g_nidx[n * T2 + s];
    } else {
        g_unmI[n * Rr + (i - Rr)] = se[i];
    }
}

// ---------------- merges ----------------
__global__ void merge_unm_kernel() {
    int n = blockIdx.y, u = blockIdx.x, tid = threadIdx.x;
    int s = g_unmI[n * Rr + u];
    const float* in = g_h + ((size_t)n * Tk + 2 * s) * Dd;
    float* out = g_hm + ((size_t)n * TNEW + u) * Dd;
    #pragma unroll
    for (int i = 0; i < 4; i++) out[tid + i * 128] = in[tid + i * 128];
}

__global__ void merge_dst_kernel() {
    int n = blockIdx.y, j = blockIdx.x, tid = threadIdx.x;
    __shared__ int sd[Rr], ss[Rr];
    if (tid < Rr) { sd[tid] = g_dstI[n * Rr + tid]; ss[tid] = g_srcI[n * Rr + tid]; }
    __syncthreads();
    const float* base = g_h + (size_t)n * Tk * Dd;
    float acc[4];
    #pragma unroll
    for (int i = 0; i < 4; i++) acc[i] = base[(size_t)(2 * j + 1) * Dd + tid + i * 128];
    int cnt = 0;
    for (int s = 0; s < Rr; s++) {
        if (sd[s] == j) {
            cnt++;
            const float* sp = base + (size_t)(2 * ss[s]) * Dd;
            #pragma unroll
            for (int i = 0; i < 4; i++) acc[i] += sp[tid + i * 128];
        }
    }
    float inv = 1.f / (float)(1 + cnt);
    float* out = g_hm + ((size_t)n * TNEW + Rr + j) * Dd;
    #pragma unroll
    for (int i = 0; i < 4; i++) out[tid + i * 128] = acc[i] * inv;
}

// ---------------- launch ----------------
extern "C" void kernel_launch(void* const* d_in, const int* in_sizes, int n_in,
                              void* d_out, int out_size) {
    const float* x      = (const float*)d_in[0];
    const float* qkv_w  = (const float*)d_in[1];
    const float* qkv_b  = (const float*)d_in[2];
    const float* proj_w = (const float*)d_in[3];
    const float* proj_b = (const float*)d_in[4];
    const float* fc1_w  = (const float*)d_in[5];
    const float* fc1_b  = (const float*)d_in[6];
    const float* fc2_w  = (const float*)d_in[7];
    const float* fc2_b  = (const float*)d_in[8];
    const float* n1_w   = (const float*)d_in[9];
    const float* n1_b   = (const float*)d_in[10];
    const float* n2_w   = (const float*)d_in[11];
    const float* n2_b   = (const float*)d_in[12];
    float* out = (float*)d_out;

    float *ph, *py, *pqkv, *pS, *phm, *pkf;
    float2* pstats;
    cudaGetSymbolAddress((void**)&ph,    g_h);
    cudaGetSymbolAddress((void**)&py,    g_y);
    cudaGetSymbolAddress((void**)&pqkv,  g_qkv);
    cudaGetSymbolAddress((void**)&pS,    g_S);
    cudaGetSymbolAddress((void**)&phm,   g_hm);
    cudaGetSymbolAddress((void**)&pkf,   g_kf);
    cudaGetSymbolAddress((void**)&pstats,g_stats);

    const long long QKV_SN = (long long)Tk * DQKV;
    const long long KF_SN  = (long long)Tk * Dd;
    const long long S_SH   = (long long)Tk * Tk;
    const long long S_SN   = (long long)Hh * Tk * Tk;
    const long long O_SN   = (long long)Tk * Dd;

    // async tf32 GEMM, 256x128: 3 stages * (256+128) rows * 20 floats * 4B = 92160 B
    constexpr int ASMEM = 3 * (256 + 128) * 20 * 4;
    cudaFuncSetAttribute(tgemm_async_kernel<256,128,16,4,2,false,false,3,1>,
                         cudaFuncAttributeMaxDynamicSharedMemorySize, ASMEM);
    cudaFuncSetAttribute(tgemm_async_kernel<256,128,16,4,2,false,true,3,1>,
                         cudaFuncAttributeMaxDynamicSharedMemorySize, ASMEM);
    cudaFuncSetAttribute(tgemm_async_kernel<256,128,16,4,2,true,false,3,1>,
                         cudaFuncAttributeMaxDynamicSharedMemorySize, ASMEM);

    // 1. permute x -> h
    permute_in_kernel<<<dim3(Dd / 256, Cc, Bn), 256>>>(x);
    // 2. LN1
    ln_kernel<<<M1, 128>>>(ph, py, n1_w, n1_b);
    // 3a. Q = y @ qkv_w[0:512]^T + b   (tf32 async 256x128)
    tgemm_async_kernel<256,128,16,4,2,false,false,3,1><<<dim3(Dd/128, M1/256, 1), 256, ASMEM>>>(
        Dd, py, Dd, 0, 0, qkv_w, Dd, 0, 0, pqkv, DQKV, 0, 0,
        1, qkv_b, 1.f, nullptr, 0);
    // 3b. V = y @ qkv_w[1024:1536]^T + b   (tf32 async 256x128)
    tgemm_async_kernel<256,128,16,4,2,false,false,3,1><<<dim3(Dd/128, M1/256, 1), 256, ASMEM>>>(
        Dd, py, Dd, 0, 0, qkv_w + (size_t)2 * Dd * Dd, Dd, 0, 0, pqkv + 2 * Dd, DQKV, 0, 0,
        1, qkv_b + 2 * Dd, 1.f, nullptr, 0);
    // 3c. K in fp32 (serial-k accum) — sole source for routing AND attention K.
    gemm_kernel<128,128,16,8,8,true,false,false><<<dim3(Dd/128, M1/128, 1), 256>>>(
        Dd, py, Dd, 0, 0, qkv_w + (size_t)Dd * Dd, Dd, 0, 0, pkf, Dd, 0, 0,
        1, qkv_b + Dd, 1.f, nullptr, 0);
    // 3d. metric (bit-stable summation order + normalize)
    metric_kernel<<<M1, HD>>>();
    // 4. S = (1/8) * Q @ K^T  (tf32 async 256x128, batched over n*H = 512)
    tgemm_async_kernel<256,128,16,4,2,false,false,3,1><<<dim3(Tk/128, Tk/256, Nn*Hh), 256, ASMEM>>>(
        HD, pqkv, DQKV, QKV_SN, HD,
            pkf,  Dd,   KF_SN,  HD,
            pS,   Tk,   S_SN,   S_SH,
        Hh, nullptr, 0.125f, nullptr, 0);
    // 5. softmax stats (row max + 1/sum)
    softmax_stats_kernel<<<NROW / 8, 256>>>();
    // 6. O = softmax(S) @ V  (tf32; exp fused into A staging) -> g_y
    tgemm_kernel<128,64,16,4,2,false,false,false,true,2><<<dim3(1, Tk/128, Nn*Hh), 256>>>(
        Tk, pS,            Tk,   S_SN,   S_SH,
            pqkv + 2 * Dd, DQKV, QKV_SN, HD,
            py,            Dd,   O_SN,   HD,
        Hh, nullptr, 1.f, nullptr, 0, pstats);
    // 7. h = h + O @ proj_w^T + b  (tf32 async 256x128, residual)
    tgemm_async_kernel<256,128,16,4,2,false,true,3,1><<<dim3(Dd/128, M1/256, 1), 256, ASMEM>>>(
        Dd, py, Dd, 0, 0, proj_w, Dd, 0, 0, ph, Dd, 0, 0,
        1, proj_b, 1.f, ph, Dd);
    // 8-10. routing (fp32-exact metric)
    node_kernel<<<dim3(T2, Nn), 256>>>();
    sort_kernel<<<Nn, 256>>>();
    merge_unm_kernel<<<dim3(Rr, Nn), 128>>>();
    merge_dst_kernel<<<dim3(T2, Nn), 128>>>();
    // 11. LN2
    ln_kernel<<<M2, 128>>>(phm, py, n2_w, n2_b);
    // 12. fc1 + GELU (tf32 async 256x128; act aliases g_S)
    tgemm_async_kernel<256,128,16,4,2,true,false,3,1><<<dim3(DFF/128, M2/256, 1), 256, ASMEM>>>(
        Dd, py, Dd, 0, 0, fc1_w, Dd, 0, 0, pS, DFF, 0, 0,
        1, fc1_b, 1.f, nullptr, 0);
    // 13. h = hm + act @ fc2_w^T + b (tf32 async 256x128, residual)
    tgemm_async_kernel<256,128,16,4,2,false,true,3,1><<<dim3(Dd/128, M2/256, 1), 256, ASMEM>>>(
        DFF, pS, DFF, 0, 0, fc2_w, DFF, 0, 0, ph, Dd, 0, 0,
        1, fc2_b, 1.f, phm, Dd);
    // 14. permute to output (B, 384, D, T)
    permute_out_kernel<<<dim3(Dd / 256, TNEW, Bn), 256>>>(out);
}

// round 17
// speedup vs baseline: 1.0208x; 1.0208x over previous
#include <cuda_runtime.h>
#include <math.h>
#include <stddef.h>
#include <stdint.h>

// ---------------- problem constants (fixed shapes) ----------------
constexpr int Bn   = 4;
constexpr int Cc   = 512;
constexpr int Dd   = 512;
constexpr int Tt   = 16;
constexpr int Nn   = Bn * Tt;      // 64 sequences
constexpr int Tk   = Cc;           // 512 tokens
constexpr int Hh   = 8;
constexpr int HD   = 64;
constexpr int DQKV = 3 * Dd;       // 1536
constexpr int DFF  = 2048;
constexpr int Rr   = 128;
constexpr int T2   = Tk / 2;       // 256
constexpr int TNEW = Tk - Rr;      // 384
constexpr int M1   = Nn * Tk;      // 32768
constexpr int M2   = Nn * TNEW;    // 24576
constexpr int NROW = Nn * Hh * Tk; // 262144 attention rows

// ---------------- scratch (__device__ globals; no allocation) ----------------
__device__ float  g_h   [(size_t)M1 * Dd];
__device__ float  g_y   [(size_t)M1 * Dd];
__device__ float  g_qkv [(size_t)M1 * DQKV];
__device__ float  g_kf  [(size_t)M1 * Dd];          // fp32-exact k block (routing + attention K)
__device__ float  g_S   [(size_t)Nn * Hh * Tk * Tk];
__device__ float2 g_stats[NROW];                     // per-row {max, 1/sum}
__device__ float  g_m   [(size_t)M1 * HD];
__device__ float  g_hm  [(size_t)M2 * Dd];
__device__ float  g_nmax[Nn * T2];
__device__ int    g_nidx[Nn * T2];
__device__ int    g_srcI[Nn * Rr];
__device__ int    g_dstI[Nn * Rr];
__device__ int    g_unmI[Nn * Rr];

// ---------------- tf32 / async helpers ----------------
__device__ __forceinline__ float to_tf32(float x) {
    uint32_t u;
    asm("cvt.rna.tf32.f32 %0, %1;" : "=r"(u) : "f"(x));
    return __uint_as_float(u);
}
__device__ __forceinline__ float4 to_tf32_4(float4 v) {
    v.x = to_tf32(v.x); v.y = to_tf32(v.y); v.z = to_tf32(v.z); v.w = to_tf32(v.w);
    return v;
}
__device__ __forceinline__ float4 exp_stats_4(float4 v, float2 st) {
    v.x = __expf(v.x - st.x) * st.y;
    v.y = __expf(v.y - st.x) * st.y;
    v.z = __expf(v.z - st.x) * st.y;
    v.w = __expf(v.w - st.x) * st.y;
    return v;
}
__device__ __forceinline__ void mma_tf32(float* c, const uint32_t* a, const uint32_t* b) {
    asm volatile(
        "mma.sync.aligned.m16n8k8.row.col.f32.tf32.tf32.f32 "
        "{%0,%1,%2,%3}, {%4,%5,%6,%7}, {%8,%9}, {%0,%1,%2,%3};"
        : "+f"(c[0]), "+f"(c[1]), "+f"(c[2]), "+f"(c[3])
        : "r"(a[0]), "r"(a[1]), "r"(a[2]), "r"(a[3]), "r"(b[0]), "r"(b[1]));
}
__device__ __forceinline__ uint32_t fbits(float x) { return __float_as_uint(x); }
// .cg: bypass L1 allocation — frees l1tex bandwidth for LDS fragment loads.
__device__ __forceinline__ void cp_async16(void* s, const void* g) {
    uint32_t sa = (uint32_t)__cvta_generic_to_shared(s);
    asm volatile("cp.async.cg.shared.global [%0], [%1], 16;\n" :: "r"(sa), "l"(g));
}
__device__ __forceinline__ void cp_commit() {
    asm volatile("cp.async.commit_group;\n");
}
template<int N>
__device__ __forceinline__ void cp_wait() {
    asm volatile("cp.async.wait_group %0;\n" :: "n"(N));
}

// ---------------- permutes ----------------
__global__ void permute_in_kernel(const float* __restrict__ x) {
    __shared__ float tile[256 * 17];
    int b = blockIdx.z, c = blockIdx.y, d0 = blockIdx.x * 256;
    int tid = threadIdx.x;
    const float* src = x + ((size_t)(b * Cc + c) * Dd + d0) * Tt;
    #pragma unroll
    for (int it = 0; it < 16; it++) {
        int l = tid + it * 256;
        tile[(l >> 4) * 17 + (l & 15)] = src[l];
    }
    __syncthreads();
    #pragma unroll
    for (int tt = 0; tt < 16; tt++) {
        g_h[((size_t)(b * Tt + tt) * Tk + c) * Dd + d0 + tid] = tile[tid * 17 + tt];
    }
}

__global__ void permute_out_kernel(float* __restrict__ out) {
    __shared__ float tile[256 * 17];
    int b = blockIdx.z, tn = blockIdx.y, d0 = blockIdx.x * 256;
    int tid = threadIdx.x;
    #pragma unroll
    for (int tt = 0; tt < 16; tt++) {
        tile[tid * 17 + tt] = g_h[((size_t)(b * Tt + tt) * TNEW + tn) * Dd + d0 + tid];
    }
    __syncthreads();
    float* dst = out + ((size_t)(b * TNEW + tn) * Dd + d0) * Tt;
    #pragma unroll
    for (int it = 0; it < 16; it++) {
        int l = tid + it * 256;
        dst[l] = tile[(l >> 4) * 17 + (l & 15)];
    }
}

// ---------------- layernorm ----------------
__global__ void ln_kernel(const float* __restrict__ in, float* __restrict__ out,
                          const float* __restrict__ w, const float* __restrict__ bb) {
    int row = blockIdx.x;
    int tid = threadIdx.x;
    const float* x = in + (size_t)row * Dd;
    float v[4];
    float s = 0.f;
    #pragma unroll
    for (int i = 0; i < 4; i++) { v[i] = x[tid + i * 128]; s += v[i]; }
    __shared__ float red[4];
    #pragma unroll
    for (int o = 16; o; o >>= 1) s += __shfl_xor_sync(0xffffffffu, s, o);
    if ((tid & 31) == 0) red[tid >> 5] = s;
    __syncthreads();
    s = red[0] + red[1] + red[2] + red[3];
    float mean = s * (1.f / 512.f);
    float s2 = 0.f;
    #pragma unroll
    for (int i = 0; i < 4; i++) { float t = v[i] - mean; s2 += t * t; }
    #pragma unroll
    for (int o = 16; o; o >>= 1) s2 += __shfl_xor_sync(0xffffffffu, s2, o);
    __syncthreads();
    if ((tid & 31) == 0) red[tid >> 5] = s2;
    __syncthreads();
    s2 = red[0] + red[1] + red[2] + red[3];
    float inv = rsqrtf(s2 * (1.f / 512.f) + 1e-6f);
    float* o = out + (size_t)row * Dd;
    #pragma unroll
    for (int i = 0; i < 4; i++) {
        int c = tid + i * 128;
        o[c] = (v[i] - mean) * inv * w[c] + bb[c];
    }
}

// ---------------- fp32 GEMM (routing path; bit-stable serial-k accumulation) ---
template<int BM, int BN, int BK, int TM, int TN, bool TRANSB, bool GELU, bool RESID>
__global__ __launch_bounds__(256, 2) void gemm_kernel(
    int K,
    const float* __restrict__ A, int lda, long long aSN, long long aSH,
    const float* __restrict__ B, int ldb, long long bSN, long long bSH,
    float*       __restrict__ C, int ldc, long long cSN, long long cSH,
    int Hdiv, const float* __restrict__ bias, float alpha,
    const float* __restrict__ resid, int ldr)
{
    constexpr int SEGM = TM / 4;
    constexpr int SEGN = TN / 4;
    static_assert(BM == 64 * SEGM && BN == 64 * SEGN, "layout requires 16x16 threads");
    __shared__ __align__(16) float As[2][BK][BM + 4];
    __shared__ __align__(16) float Bs[2][BK][BN + 4];
    int z = blockIdx.z;
    int zn = z / Hdiv, zh = z - zn * Hdiv;
    A += zn * aSN + zh * aSH;
    B += zn * bSN + zh * bSH;
    C += zn * cSN + zh * cSH;
    int row0 = blockIdx.y * BM, col0 = blockIdx.x * BN;
    int tid = threadIdx.x;
    int tx = tid % 16, ty = tid / 16;

    constexpr int KV = BK / 4;
    constexpr int AV = BM * BK / 1024;
    constexpr int BV = BN * BK / 1024;

    int am = tid / KV,  ak = (tid % KV) * 4;
    int am2 = (tid + 256) / KV, ak2 = ((tid + 256) % KV) * 4;
    int bn_t = tid / KV,            bk_t = (tid % KV) * 4;
    int bn_t2 = (tid + 256) / KV,   bk_t2 = ((tid + 256) % KV) * 4;
    int bk_n = tid / (BN / 4),      bn_n = (tid % (BN / 4)) * 4;
    int bk_n2 = (tid + 256) / (BN / 4), bn_n2 = ((tid + 256) % (BN / 4)) * 4;

    float4 ra[AV], rb[BV];
    float acc[TM][TN];
    #pragma unroll
    for (int i = 0; i < TM; i++)
        #pragma unroll
        for (int j = 0; j < TN; j++) acc[i][j] = 0.f;

    float (*Asc)[BM + 4] = As[0];
    float (*Asn)[BM + 4] = As[1];
    float (*Bsc)[BN + 4] = Bs[0];
    float (*Bsn)[BN + 4] = Bs[1];

    {
        ra[0] = *(const float4*)(A + (size_t)(row0 + am) * lda + ak);
        if (AV > 1) ra[1] = *(const float4*)(A + (size_t)(row0 + am2) * lda + ak2);
        if (TRANSB) {
            rb[0] = *(const float4*)(B + (size_t)(col0 + bn_t) * ldb + bk_t);
            if (BV > 1) rb[1] = *(const float4*)(B + (size_t)(col0 + bn_t2) * ldb + bk_t2);
        } else {
            rb[0] = *(const float4*)(B + (size_t)bk_n * ldb + col0 + bn_n);
            if (BV > 1) rb[1] = *(const float4*)(B + (size_t)bk_n2 * ldb + col0 + bn_n2);
        }
        Asc[ak + 0][am] = ra[0].x; Asc[ak + 1][am] = ra[0].y;
        Asc[ak + 2][am] = ra[0].z; Asc[ak + 3][am] = ra[0].w;
        if (AV > 1) {
            Asc[ak2 + 0][am2] = ra[1].x; Asc[ak2 + 1][am2] = ra[1].y;
            Asc[ak2 + 2][am2] = ra[1].z; Asc[ak2 + 3][am2] = ra[1].w;
        }
        if (TRANSB) {
            Bsc[bk_t + 0][bn_t] = rb[0].x; Bsc[bk_t + 1][bn_t] = rb[0].y;
            Bsc[bk_t + 2][bn_t] = rb[0].z; Bsc[bk_t + 3][bn_t] = rb[0].w;
            if (BV > 1) {
                Bsc[bk_t2 + 0][bn_t2] = rb[1].x; Bsc[bk_t2 + 1][bn_t2] = rb[1].y;
                Bsc[bk_t2 + 2][bn_t2] = rb[1].z; Bsc[bk_t2 + 3][bn_t2] = rb[1].w;
            }
        } else {
            *(float4*)&Bsc[bk_n][bn_n] = rb[0];
            if (BV > 1) *(float4*)&Bsc[bk_n2][bn_n2] = rb[1];
        }
    }
    __syncthreads();

    for (int k0 = BK; k0 < K; k0 += BK) {
        ra[0] = *(const float4*)(A + (size_t)(row0 + am) * lda + k0 + ak);
        if (AV > 1) ra[1] = *(const float4*)(A + (size_t)(row0 + am2) * lda + k0 + ak2);
        if (TRANSB) {
            rb[0] = *(const float4*)(B + (size_t)(col0 + bn_t) * ldb + k0 + bk_t);
            if (BV > 1) rb[1] = *(const float4*)(B + (size_t)(col0 + bn_t2) * ldb + k0 + bk_t2);
        } else {
            rb[0] = *(const float4*)(B + (size_t)(k0 + bk_n) * ldb + col0 + bn_n);
            if (BV > 1) rb[1] = *(const float4*)(B + (size_t)(k0 + bk_n2) * ldb + col0 + bn_n2);
        }
        #pragma unroll
        for (int k = 0; k < BK; k++) {
            float rm[TM], rn[TN];
            #pragma unroll
            for (int s = 0; s < SEGM; s++)
                *(float4*)&rm[s * 4] = *(const float4*)&Asc[k][ty * 4 + s * 64];
            #pragma unroll
            for (int s = 0; s < SEGN; s++)
                *(float4*)&rn[s * 4] = *(const float4*)&Bsc[k][tx * 4 + s * 64];
            #pragma unroll
            for (int i = 0; i < TM; i++)
                #pragma unroll
                for (int j = 0; j < TN; j++)
                    acc[i][j] += rm[i] * rn[j];
        }
        Asn[ak + 0][am] = ra[0].x; Asn[ak + 1][am] = ra[0].y;
        Asn[ak + 2][am] = ra[0].z; Asn[ak + 3][am] = ra[0].w;
        if (AV > 1) {
            Asn[ak2 + 0][am2] = ra[1].x; Asn[ak2 + 1][am2] = ra[1].y;
            Asn[ak2 + 2][am2] = ra[1].z; Asn[ak2 + 3][am2] = ra[1].w;
        }
        if (TRANSB) {
            Bsn[bk_t + 0][bn_t] = rb[0].x; Bsn[bk_t + 1][bn_t] = rb[0].y;
            Bsn[bk_t + 2][bn_t] = rb[0].z; Bsn[bk_t + 3][bn_t] = rb[0].w;
            if (BV > 1) {
                Bsn[bk_t2 + 0][bn_t2] = rb[1].x; Bsn[bk_t2 + 1][bn_t2] = rb[1].y;
                Bsn[bk_t2 + 2][bn_t2] = rb[1].z; Bsn[bk_t2 + 3][bn_t2] = rb[1].w;
            }
        } else {
            *(float4*)&Bsn[bk_n][bn_n] = rb[0];
            if (BV > 1) *(float4*)&Bsn[bk_n2][bn_n2] = rb[1];
        }
        __syncthreads();
        float (*t1)[BM + 4] = Asc; Asc = Asn; Asn = t1;
        float (*t2)[BN + 4] = Bsc; Bsc = Bsn; Bsn = t2;
    }
    #pragma unroll
    for (int k = 0; k < BK; k++) {
        float rm[TM], rn[TN];
        #pragma unroll
        for (int s = 0; s < SEGM; s++)
            *(float4*)&rm[s * 4] = *(const float4*)&Asc[k][ty * 4 + s * 64];
        #pragma unroll
        for (int s = 0; s < SEGN; s++)
            *(float4*)&rn[s * 4] = *(const float4*)&Bsc[k][tx * 4 + s * 64];
        #pragma unroll
        for (int i = 0; i < TM; i++)
            #pragma unroll
            for (int j = 0; j < TN; j++)
                acc[i][j] += rm[i] * rn[j];
    }

    #pragma unroll
    for (int si = 0; si < SEGM; si++) {
        #pragma unroll
        for (int i2 = 0; i2 < 4; i2++) {
            int r = row0 + ty * 4 + si * 64 + i2;
            int i = si * 4 + i2;
            #pragma unroll
            for (int sj = 0; sj < SEGN; sj++) {
                int c = col0 + tx * 4 + sj * 64;
                float4 v;
                v.x = acc[i][sj * 4 + 0] * alpha;
                v.y = acc[i][sj * 4 + 1] * alpha;
                v.z = acc[i][sj * 4 + 2] * alpha;
                v.w = acc[i][sj * 4 + 3] * alpha;
                if (bias) {
                    float4 bv = *(const float4*)(bias + c);
                    v.x += bv.x; v.y += bv.y; v.z += bv.z; v.w += bv.w;
                }
                if (GELU) {
                    v.x = 0.5f * v.x * (1.f + erff(v.x * 0.70710678118654752f));
                    v.y = 0.5f * v.y * (1.f + erff(v.y * 0.70710678118654752f));
                    v.z = 0.5f * v.z * (1.f + erff(v.z * 0.70710678118654752f));
                    v.w = 0.5f * v.w * (1.f + erff(v.w * 0.70710678118654752f));
                }
                if (RESID) {
                    float4 rv = *(const float4*)(resid + (size_t)r * ldr + c);
                    v.x += rv.x; v.y += rv.y; v.z += rv.z; v.w += rv.w;
                }
                *(float4*)(C + (size_t)r * ldc + c) = v;
            }
        }
    }
}

// ---------------- tf32 async GEMM: cp.async.cg 4-stage, 128x128 ---------------
// Raw fp32 staged via LDGSTS (.cg — no L1 fill); HMMA.TF32 truncates operands.
template<int BM, int BN, int BK, int WM, int WN, bool GELU, bool RESID, int STAGES>
__global__ __launch_bounds__(256, 2) void tgemm_async_kernel(
    int K,
    const float* __restrict__ A, int lda, long long aSN, long long aSH,
    const float* __restrict__ B, int ldb, long long bSN, long long bSH,
    float*       __restrict__ C, int ldc, long long cSN, long long cSH,
    int Hdiv, const float* __restrict__ bias, float alpha,
    const float* __restrict__ resid, int ldr)
{
    constexpr int KP  = BK + 4;
    constexpr int WTM = BM / WM;
    constexpr int WTN = BN / WN;
    constexpr int MF  = WTM / 16;
    constexpr int NF  = WTN / 8;
    constexpr int KV  = BK / 4;
    static_assert(WM * WN == 8, "8 warps");
    static_assert(BM == 128 && BN == 128 && BK == 16, "fixed cfg");

    extern __shared__ float smem[];
    float* As = smem;                          // STAGES * BM * KP
    float* Bs = smem + STAGES * BM * KP;       // STAGES * BN * KP

    int z = blockIdx.z;
    int zn = z / Hdiv, zh = z - zn * Hdiv;
    A += zn * aSN + zh * aSH;
    B += zn * bSN + zh * bSH;
    C += zn * cSN + zh * cSH;
    int row0 = blockIdx.y * BM, col0 = blockIdx.x * BN;
    int tid = threadIdx.x;
    int wid = tid >> 5, lane = tid & 31;
    int wm = (wid / WN) * WTM, wn = (wid % WN) * WTN;
    int gid = lane >> 2, tig = lane & 3;

    int am = tid / KV, ak = (tid % KV) * 4;

    const float* Ap0 = A + (size_t)(row0 + am) * lda + ak;
    const float* Ap1 = Ap0 + (size_t)64 * lda;
    const float* Bp0 = B + (size_t)(col0 + am) * ldb + ak;
    const float* Bp1 = Bp0 + (size_t)64 * ldb;
    float* Asd0 = As + (size_t)am * KP + ak;
    float* Asd1 = Asd0 + (size_t)64 * KP;
    float* Bsd0 = Bs + (size_t)am * KP + ak;
    float* Bsd1 = Bsd0 + (size_t)64 * KP;

    float acc[MF][NF][4];
    #pragma unroll
    for (int f = 0; f < MF; f++)
        #pragma unroll
        for (int j = 0; j < NF; j++)
            #pragma unroll
            for (int q = 0; q < 4; q++) acc[f][j][q] = 0.f;

    const int NC = K / BK;

    // prologue: issue first STAGES-1 chunks (or fewer if K is short)
    #pragma unroll
    for (int s = 0; s < STAGES - 1; s++) {
        if (s < NC) {
            int k0 = s * BK;
            cp_async16(Asd0 + s * BM * KP, Ap0 + k0);
            cp_async16(Asd1 + s * BM * KP, Ap1 + k0);
            cp_async16(Bsd0 + s * BN * KP, Bp0 + k0);
            cp_async16(Bsd1 + s * BN * KP, Bp1 + k0);
        }
        cp_commit();
    }

    for (int c = 0; c < NC; c++) {
        cp_wait<STAGES - 2>();
        __syncthreads();
        int cn = c + STAGES - 1;
        if (cn < NC) {
            int s = cn % STAGES;
            int k0 = cn * BK;
            cp_async16(Asd0 + s * BM * KP, Ap0 + k0);
            cp_async16(Asd1 + s * BM * KP, Ap1 + k0);
            cp_async16(Bsd0 + s * BN * KP, Bp0 + k0);
            cp_async16(Bsd1 + s * BN * KP, Bp1 + k0);
        }
        cp_commit();
        int cs = c % STAGES;
        const uint32_t* Ast = (const uint32_t*)(As + (size_t)cs * BM * KP);
        const uint32_t* Bst = (const uint32_t*)(Bs + (size_t)cs * BN * KP);
        #pragma unroll
        for (int kk = 0; kk < BK; kk += 8) {
            uint32_t af[MF][4], bf[NF][2];
            #pragma unroll
            for (int f = 0; f < MF; f++) {
                const uint32_t* ap = Ast + (size_t)(wm + f * 16 + gid) * KP + kk + tig;
                af[f][0] = ap[0];
                af[f][1] = ap[8 * KP];
                af[f][2] = ap[4];
                af[f][3] = ap[8 * KP + 4];
            }
            #pragma unroll
            for (int j = 0; j < NF; j++) {
                const uint32_t* bp = Bst + (size_t)(wn + j * 8 + gid) * KP + kk + tig;
                bf[j][0] = bp[0];
                bf[j][1] = bp[4];
            }
            #pragma unroll
            for (int f = 0; f < MF; f++)
                #pragma unroll
                for (int j = 0; j < NF; j++)
                    mma_tf32(acc[f][j], af[f], bf[j]);
        }
    }

    // ---- epilogue ----
    #pragma unroll
    for (int f = 0; f < MF; f++) {
        #pragma unroll
        for (int half = 0; half < 2; half++) {
            int r = row0 + wm + f * 16 + gid + half * 8;
            #pragma unroll
            for (int j = 0; j < NF; j++) {
                int c = col0 + wn + j * 8 + tig * 2;
                float vx = acc[f][j][half * 2 + 0] * alpha;
                float vy = acc[f][j][half * 2 + 1] * alpha;
                if (bias) { vx += bias[c]; vy += bias[c + 1]; }
                if (GELU) {
                    vx = 0.5f * vx * (1.f + erff(vx * 0.70710678118654752f));
                    vy = 0.5f * vy * (1.f + erff(vy * 0.70710678118654752f));
                }
                if (RESID) {
                    float2 rv = *(const float2*)(resid + (size_t)r * ldr + c);
                    vx += rv.x; vy += rv.y;
                }
                float2 v; v.x = vx; v.y = vy;
                *(float2*)(C + (size_t)r * ldc + c) = v;
            }
        }
    }
}

// ---------------- tf32 tensor-core GEMM (PV / EXPA path) ----------------------
template<int BM, int BN, int BK, int WM, int WN, bool TRANSB, bool GELU, bool RESID, bool EXPA, int MINB>
__global__ __launch_bounds__(256, MINB) void tgemm_kernel(
    int K,
    const float* __restrict__ A, int lda, long long aSN, long long aSH,
    const float* __restrict__ B, int ldb, long long bSN, long long bSH,
    float*       __restrict__ C, int ldc, long long cSN, long long cSH,
    int Hdiv, const float* __restrict__ bias, float alpha,
    const float* __restrict__ resid, int ldr,
    const float2* __restrict__ stats)
{
    constexpr int KP  = BK + 4;
    constexpr int WTM = BM / WM;
    constexpr int WTN = BN / WN;
    constexpr int MF  = WTM / 16;
    constexpr int NF  = WTN / 8;
    constexpr int KV  = BK / 4;
    constexpr int AV  = BM * BK / 1024;
    constexpr int BV  = BN * BK / 1024;
    constexpr int BROWS = 1024 / BN;
    static_assert(WM * WN == 8, "8 warps");

    __shared__ __align__(16) float As[2][BM][KP];
    __shared__ __align__(16) float Bs[2][BN][KP];

    int z = blockIdx.z;
    int zn = z / Hdiv, zh = z - zn * Hdiv;
    A += zn * aSN + zh * aSH;
    B += zn * bSN + zh * bSH;
    C += zn * cSN + zh * cSH;
    int row0 = blockIdx.y * BM, col0 = blockIdx.x * BN;
    int tid = threadIdx.x;
    int wid = tid >> 5, lane = tid & 31;
    int wm = (wid / WN) * WTM, wn = (wid % WN) * WTN;
    int gid = lane >> 2, tig = lane & 3;

    int am = tid / KV,  ak = (tid % KV) * 4;
    int bn_t = tid / KV, bk_t = (tid % KV) * 4;
    int bk_n = tid / (BN / 4), bn_n = (tid % (BN / 4)) * 4;

    float2 st[AV];
    #pragma unroll
    for (int v = 0; v < AV; v++) st[v] = make_float2(0.f, 1.f);
    if (EXPA) {
        #pragma unroll
        for (int v = 0; v < AV; v++)
            st[v] = stats[(size_t)z * Tk + row0 + am + v * 64];
    }

    float4 ra[AV], rb[BV];
    float acc[MF][NF][4];
    #pragma unroll
    for (int f = 0; f < MF; f++)
        #pragma unroll
        for (int j = 0; j < NF; j++)
            #pragma unroll
            for (int q = 0; q < 4; q++) acc[f][j][q] = 0.f;

    float (*Asc)[KP] = As[0];
    float (*Asn)[KP] = As[1];
    float (*Bsc)[KP] = Bs[0];
    float (*Bsn)[KP] = Bs[1];

    {
        #pragma unroll
        for (int v = 0; v < AV; v++)
            ra[v] = *(const float4*)(A + (size_t)(row0 + am + v * 64) * lda + ak);
        if (TRANSB) {
            #pragma unroll
            for (int v = 0; v < BV; v++)
                rb[v] = *(const float4*)(B + (size_t)(col0 + bn_t + v * 64) * ldb + bk_t);
        } else {
            #pragma unroll
            for (int v = 0; v < BV; v++)
                rb[v] = *(const float4*)(B + (size_t)(bk_n + v * BROWS) * ldb + col0 + bn_n);
        }
        #pragma unroll
        for (int v = 0; v < AV; v++) {
            float4 t = ra[v];
            if (EXPA) t = exp_stats_4(t, st[v]);
            *(float4*)&Asc[am + v * 64][ak] = to_tf32_4(t);
        }
        if (TRANSB) {
            #pragma unroll
            for (int v = 0; v < BV; v++)
                *(float4*)&Bsc[bn_t + v * 64][bk_t] = to_tf32_4(rb[v]);
        } else {
            #pragma unroll
            for (int v = 0; v < BV; v++) {
                float4 t = to_tf32_4(rb[v]);
                int bk2 = bk_n + v * BROWS;
                Bsc[bn_n + 0][bk2] = t.x; Bsc[bn_n + 1][bk2] = t.y;
                Bsc[bn_n + 2][bk2] = t.z; Bsc[bn_n + 3][bk2] = t.w;
            }
        }
    }
    __syncthreads();

    for (int k0 = BK; k0 < K; k0 += BK) {
        #pragma unroll
        for (int v = 0; v < AV; v++)
            ra[v] = *(const float4*)(A + (size_t)(row0 + am + v * 64) * lda + k0 + ak);
        if (TRANSB) {
            #pragma unroll
            for (int v = 0; v < BV; v++)
                rb[v] = *(const float4*)(B + (size_t)(col0 + bn_t + v * 64) * ldb + k0 + bk_t);
        } else {
            #pragma unroll
            for (int v = 0; v < BV; v++)
                rb[v] = *(const float4*)(B + (size_t)(k0 + bk_n + v * BROWS) * ldb + col0 + bn_n);
        }
        #pragma unroll
        for (int kk = 0; kk < BK; kk += 8) {
            uint32_t af[MF][4], bf[NF][2];
            #pragma unroll
            for (int f = 0; f < MF; f++) {
                const float* ap = &Asc[wm + f * 16 + gid][kk + tig];
                af[f][0] = fbits(ap[0]);
                af[f][1] = fbits(ap[8 * KP]);
                af[f][2] = fbits(ap[4]);
                af[f][3] = fbits(ap[8 * KP + 4]);
            }
            #pragma unroll
            for (int j = 0; j < NF; j++) {
                const float* bp = &Bsc[wn + j * 8 + gid][kk + tig];
                bf[j][0] = fbits(bp[0]);
                bf[j][1] = fbits(bp[4]);
            }
            #pragma unroll
            for (int f = 0; f < MF; f++)
                #pragma unroll
                for (int j = 0; j < NF; j++)
                    mma_tf32(acc[f][j], af[f], bf[j]);
        }
        #pragma unroll
        for (int v = 0; v < AV; v++) {
            float4 t = ra[v];
            if (EXPA) t = exp_stats_4(t, st[v]);
            *(float4*)&Asn[am + v * 64][ak] = to_tf32_4(t);
        }
        if (TRANSB) {
            #pragma unroll
            for (int v = 0; v < BV; v++)
                *(float4*)&Bsn[bn_t + v * 64][bk_t] = to_tf32_4(rb[v]);
        } else {
            #pragma unroll
            for (int v = 0; v < BV; v++) {
                float4 t = to_tf32_4(rb[v]);
                int bk2 = bk_n + v * BROWS;
                Bsn[bn_n + 0][bk2] = t.x; Bsn[bn_n + 1][bk2] = t.y;
                Bsn[bn_n + 2][bk2] = t.z; Bsn[bn_n + 3][bk2] = t.w;
            }
        }
        __syncthreads();
        float (*t1)[KP] = Asc; Asc = Asn; Asn = t1;
        float (*t2)[KP] = Bsc; Bsc = Bsn; Bsn = t2;
    }
    #pragma unroll
    for (int kk = 0; kk < BK; kk += 8) {
        uint32_t af[MF][4], bf[NF][2];
        #pragma unroll
        for (int f = 0; f < MF; f++) {
            const float* ap = &Asc[wm + f * 16 + gid][kk + tig];
            af[f][0] = fbits(ap[0]);
            af[f][1] = fbits(ap[8 * KP]);
            af[f][2] = fbits(ap[4]);
            af[f][3] = fbits(ap[8 * KP + 4]);
        }
        #pragma unroll
        for (int j = 0; j < NF; j++) {
            const float* bp = &Bsc[wn + j * 8 + gid][kk + tig];
            bf[j][0] = fbits(bp[0]);
            bf[j][1] = fbits(bp[4]);
        }
        #pragma unroll
        for (int f = 0; f < MF; f++)
            #pragma unroll
            for (int j = 0; j < NF; j++)
                mma_tf32(acc[f][j], af[f], bf[j]);
    }

    #pragma unroll
    for (int f = 0; f < MF; f++) {
        #pragma unroll
        for (int half = 0; half < 2; half++) {
            int r = row0 + wm + f * 16 + gid + half * 8;
            #pragma unroll
            for (int j = 0; j < NF; j++) {
                int c = col0 + wn + j * 8 + tig * 2;
                float vx = acc[f][j][half * 2 + 0] * alpha;
                float vy = acc[f][j][half * 2 + 1] * alpha;
                if (bias) { vx += bias[c]; vy += bias[c + 1]; }
                if (GELU) {
                    vx = 0.5f * vx * (1.f + erff(vx * 0.70710678118654752f));
                    vy = 0.5f * vy * (1.f + erff(vy * 0.70710678118654752f));
                }
                if (RESID) {
                    float2 rv = *(const float2*)(resid + (size_t)r * ldr + c);
                    vx += rv.x; vy += rv.y;
                }
                float2 v; v.x = vx; v.y = vy;
                *(float2*)(C + (size_t)r * ldc + c) = v;
            }
        }
    }
}

// ---------------- metric = mean_h(k), L2-normalized (bit-stable order) ---------
__global__ void metric_kernel() {
    int token = blockIdx.x;
    int d = threadIdx.x;        // 64
    const float* base = g_kf + (size_t)token * Dd + d;
    float v = 0.f;
    #pragma unroll
    for (int h = 0; h < Hh; h++) v += base[h * HD];
    v *= 0.125f;
    float sq = v * v;
    #pragma unroll
    for (int o = 16; o; o >>= 1) sq += __shfl_xor_sync(0xffffffffu, sq, o);
    __shared__ float ws[2];
    if ((d & 31) == 0) ws[d >> 5] = sq;
    __syncthreads();
    float tot = ws[0] + ws[1];
    g_m[(size_t)token * HD + d] = v / sqrtf(tot);
}

// ---------------- softmax stats: per-row {max, 1/sum(exp)} --------------------
__global__ void softmax_stats_kernel() {
    int gw   = (blockIdx.x * blockDim.x + threadIdx.x) >> 5;
    int lane = threadIdx.x & 31;
    const float* row = g_S + (size_t)gw * Tk;
    float v[16];
    float mx = -1e30f;
    #pragma unroll
    for (int i = 0; i < 16; i++) { v[i] = row[lane + i * 32]; mx = fmaxf(mx, v[i]); }
    #pragma unroll
    for (int o = 16; o; o >>= 1) mx = fmaxf(mx, __shfl_xor_sync(0xffffffffu, mx, o));
    float s = 0.f;
    #pragma unroll
    for (int i = 0; i < 16; i++) s += __expf(v[i] - mx);
    #pragma unroll
    for (int o = 16; o; o >>= 1) s += __shfl_xor_sync(0xffffffffu, s, o);
    if (lane == 0) g_stats[gw] = make_float2(mx, 1.f / s);
}

// ---------------- node_max / node_idx ----------------
__global__ void node_kernel() {
    int n = blockIdx.y, i = blockIdx.x;
    __shared__ float a[64];
    __shared__ float sv[256];
    __shared__ int   si[256];
    int tid = threadIdx.x;
    if (tid < 64) a[tid] = g_m[((size_t)n * Tk + 2 * i) * HD + tid];
    __syncthreads();
    const float* bj = g_m + ((size_t)n * Tk + 2 * tid + 1) * HD;
    float s = 0.f;
    #pragma unroll
    for (int d = 0; d < 64; d++) s += a[d] * bj[d];
    sv[tid] = s; si[tid] = tid;
    __syncthreads();
    for (int st = 128; st; st >>= 1) {
        if (tid < st) {
            float v2 = sv[tid + st]; int i2 = si[tid + st];
            if (v2 > sv[tid] || (v2 == sv[tid] && i2 < si[tid])) { sv[tid] = v2; si[tid] = i2; }
        }
        __syncthreads();
    }
    if (tid == 0) { g_nmax[n * T2 + i] = sv[0]; g_nidx[n * T2 + i] = si[0]; }
}

// ---------------- stable descending rank sort ----------------
__global__ void sort_kernel() {
    int n = blockIdx.x, i = threadIdx.x;
    __shared__ float k[256];
    __shared__ int   se[256];
    k[i] = g_nmax[n * T2 + i];
    __syncthreads();
    float ki = k[i];
    int r = 0;
    #pragma unroll 8
    for (int j = 0; j < 256; j++) {
        float kj = k[j];
        r += (kj > ki) || (kj == ki && j < i);
    }
    se[r] = i;
    __syncthreads();
    if (i < Rr) {
        int s = se[i];
        g_srcI[n * Rr + i] = s;
        g_dstI[n * Rr + i] = g_nidx[n * T2 + s];
    } else {
        g_unmI[n * Rr + (i - Rr)] = se[i];
    }
}

// ---------------- merges ----------------
__global__ void merge_unm_kernel() {
    int n = blockIdx.y, u = blockIdx.x, tid = threadIdx.x;
    int s = g_unmI[n * Rr + u];
    const float* in = g_h + ((size_t)n * Tk + 2 * s) * Dd;
    float* out = g_hm + ((size_t)n * TNEW + u) * Dd;
    #pragma unroll
    for (int i = 0; i < 4; i++) out[tid + i * 128] = in[tid + i * 128];
}

__global__ void merge_dst_kernel() {
    int n = blockIdx.y, j = blockIdx.x, tid = threadIdx.x;
    __shared__ int sd[Rr], ss[Rr];
    if (tid < Rr) { sd[tid] = g_dstI[n * Rr + tid]; ss[tid] = g_srcI[n * Rr + tid]; }
    __syncthreads();
    const float* base = g_h + (size_t)n * Tk * Dd;
    float acc[4];
    #pragma unroll
    for (int i = 0; i < 4; i++) acc[i] = base[(size_t)(2 * j + 1) * Dd + tid + i * 128];
    int cnt = 0;
    for (int s = 0; s < Rr; s++) {
        if (sd[s] == j) {
            cnt++;
            const float* sp = base + (size_t)(2 * ss[s]) * Dd;
            #pragma unroll
            for (int i = 0; i < 4; i++) acc[i] += sp[tid + i * 128];
        }
    }
    float inv = 1.f / (float)(1 + cnt);
    float* out = g_hm + ((size_t)n * TNEW + Rr + j) * Dd;
    #pragma unroll
    for (int i = 0; i < 4; i++) out[tid + i * 128] = acc[i] * inv;
}

// ---------------- launch ----------------
extern "C" void kernel_launch(void* const* d_in, const int* in_sizes, int n_in,
                              void* d_out, int out_size) {
    const float* x      = (const float*)d_in[0];
    const float* qkv_w  = (const float*)d_in[1];
    const float* qkv_b  = (const float*)d_in[2];
    const float* proj_w = (const float*)d_in[3];
    const float* proj_b = (const float*)d_in[4];
    const float* fc1_w  = (const float*)d_in[5];
    const float* fc1_b  = (const float*)d_in[6];
    const float* fc2_w  = (const float*)d_in[7];
    const float* fc2_b  = (const float*)d_in[8];
    const float* n1_w   = (const float*)d_in[9];
    const float* n1_b   = (const float*)d_in[10];
    const float* n2_w   = (const float*)d_in[11];
    const float* n2_b   = (const float*)d_in[12];
    float* out = (float*)d_out;

    float *ph, *py, *pqkv, *pS, *phm, *pkf;
    float2* pstats;
    cudaGetSymbolAddress((void**)&ph,    g_h);
    cudaGetSymbolAddress((void**)&py,    g_y);
    cudaGetSymbolAddress((void**)&pqkv,  g_qkv);
    cudaGetSymbolAddress((void**)&pS,    g_S);
    cudaGetSymbolAddress((void**)&phm,   g_hm);
    cudaGetSymbolAddress((void**)&pkf,   g_kf);
    cudaGetSymbolAddress((void**)&pstats,g_stats);

    const long long QKV_SN = (long long)Tk * DQKV;
    const long long KF_SN  = (long long)Tk * Dd;
    const long long S_SH   = (long long)Tk * Tk;
    const long long S_SN   = (long long)Hh * Tk * Tk;
    const long long O_SN   = (long long)Tk * Dd;

    // async tf32 GEMM: 4 stages * (128+128) rows * 20 floats * 4B = 81920 B
    constexpr int ASMEM = 4 * (128 + 128) * 20 * 4;
    cudaFuncSetAttribute(tgemm_async_kernel<128,128,16,2,4,false,false,4>,
                         cudaFuncAttributeMaxDynamicSharedMemorySize, ASMEM);
    cudaFuncSetAttribute(tgemm_async_kernel<128,128,16,2,4,false,true,4>,
                         cudaFuncAttributeMaxDynamicSharedMemorySize, ASMEM);
    cudaFuncSetAttribute(tgemm_async_kernel<128,128,16,2,4,true,false,4>,
                         cudaFuncAttributeMaxDynamicSharedMemorySize, ASMEM);

    // 1. permute x -> h
    permute_in_kernel<<<dim3(Dd / 256, Cc, Bn), 256>>>(x);
    // 2. LN1
    ln_kernel<<<M1, 128>>>(ph, py, n1_w, n1_b);
    // 3a. Q = y @ qkv_w[0:512]^T + b   (tf32 async)
    tgemm_async_kernel<128,128,16,2,4,false,false,4><<<dim3(Dd/128, M1/128, 1), 256, ASMEM>>>(
        Dd, py, Dd, 0, 0, qkv_w, Dd, 0, 0, pqkv, DQKV, 0, 0,
        1, qkv_b, 1.f, nullptr, 0);
    // 3b. V = y @ qkv_w[1024:1536]^T + b   (tf32 async)
    tgemm_async_kernel<128,128,16,2,4,false,false,4><<<dim3(Dd/128, M1/128, 1), 256, ASMEM>>>(
        Dd, py, Dd, 0, 0, qkv_w + (size_t)2 * Dd * Dd, Dd, 0, 0, pqkv + 2 * Dd, DQKV, 0, 0,
        1, qkv_b + 2 * Dd, 1.f, nullptr, 0);
    // 3c. K in fp32 (serial-k accum) — sole source for routing AND attention K.
    gemm_kernel<128,128,16,8,8,true,false,false><<<dim3(Dd/128, M1/128, 1), 256>>>(
        Dd, py, Dd, 0, 0, qkv_w + (size_t)Dd * Dd, Dd, 0, 0, pkf, Dd, 0, 0,
        1, qkv_b + Dd, 1.f, nullptr, 0);
    // 3d. metric (bit-stable summation order + normalize)
    metric_kernel<<<M1, HD>>>();
    // 4. S = (1/8) * Q @ K^T  (tf32 async, batched over n*H = 512)
    tgemm_async_kernel<128,128,16,2,4,false,false,4><<<dim3(Tk/128, Tk/128, Nn*Hh), 256, ASMEM>>>(
        HD, pqkv, DQKV, QKV_SN, HD,
            pkf,  Dd,   KF_SN,  HD,
            pS,   Tk,   S_SN,   S_SH,
        Hh, nullptr, 0.125f, nullptr, 0);
    // 5. softmax stats (row max + 1/sum)
    softmax_stats_kernel<<<NROW / 8, 256>>>();
    // 6. O = softmax(S) @ V  (tf32; exp fused into A staging) -> g_y
    tgemm_kernel<128,64,16,4,2,false,false,false,true,2><<<dim3(1, Tk/128, Nn*Hh), 256>>>(
        Tk, pS,            Tk,   S_SN,   S_SH,
            pqkv + 2 * Dd, DQKV, QKV_SN, HD,
            py,            Dd,   O_SN,   HD,
        Hh, nullptr, 1.f, nullptr, 0, pstats);
    // 7. h = h + O @ proj_w^T + b  (tf32 async, residual)
    tgemm_async_kernel<128,128,16,2,4,false,true,4><<<dim3(Dd/128, M1/128, 1), 256, ASMEM>>>(
        Dd, py, Dd, 0, 0, proj_w, Dd, 0, 0, ph, Dd, 0, 0,
        1, proj_b, 1.f, ph, Dd);
    // 8-10. routing (fp32-exact metric)
    node_kernel<<<dim3(T2, Nn), 256>>>();
    sort_kernel<<<Nn, 256>>>();
    merge_unm_kernel<<<dim3(Rr, Nn), 128>>>();
    merge_dst_kernel<<<dim3(T2, Nn), 128>>>();
    // 11. LN2
    ln_kernel<<<M2, 128>>>(phm, py, n2_w, n2_b);
    // 12. fc1 + GELU (tf32 async; act aliases g_S)
    tgemm_async_kernel<128,128,16,2,4,true,false,4><<<dim3(DFF/128, M2/128, 1), 256, ASMEM>>>(
        Dd, py, Dd, 0, 0, fc1_w, Dd, 0, 0, pS, DFF, 0, 0,
        1, fc1_b, 1.f, nullptr, 0);
    // 13. h = hm + act @ fc2_w^T + b (tf32 async, residual)
    tgemm_async_kernel<128,128,16,2,4,false,true,4><<<dim3(Dd/128, M2/128, 1), 256, ASMEM>>>(
        DFF, pS, DFF, 0, 0, fc2_w, DFF, 0, 0, ph, Dd, 0, 0,
        1, fc2_b, 1.f, phm, Dd);
    // 14. permute to output (B, 384, D, T)
    permute_out_kernel<<<dim3(Dd / 256, TNEW, Bn), 256>>>(out);
}